// round 7
// baseline (speedup 1.0000x reference)
#include <cuda_runtime.h>
#include <cstdint>

#define DIM     64
#define CHUNKS  16            // float4 chunks per row
#define NMAX    100000        // nodes per ntype (static scratch sizing)
#define EMAX    500000        // edges per relation
#define KSLOT   32            // slots per bucket (deg ~Poisson(10)); 128B aligned
#define SPILLC  (4 * EMAX)    // spill capacity = all edges (unconditional)

// ---------------------------------------------------------------------------
// scratch (device globals — zero-initialized at module load; kernels restore
// the all-zero invariant before finishing, so every launch/replay sees zeros)
// ---------------------------------------------------------------------------
__device__ int  g_nover;                      // overflow edge count
__device__ int  g_done;                       // accum finished-block ticket
__device__ int  g_cur[2 * NMAX];              // per-bucket write cursors
__device__ int  g_entries[2 * NMAX * KSLOT];  // src | (tableFlag<<30)
__device__ int2 g_spill[SPILLC];              // (bucket, src|flag<<30)

// ---------------------------------------------------------------------------
// index helpers. int64 values in [0,1e5): odd 32-bit words are 0.
// int32 random values: P(4 specific words all 0) ~ 1e-20. Broadcast loads.
// ---------------------------------------------------------------------------
__device__ __forceinline__ int probe_idx64(const unsigned int* __restrict__ w) {
    return ((w[1] | w[3] | w[5] | w[7]) == 0u) ? 1 : 0;
}
__device__ __forceinline__ int load_idx32(const void* p, int i, int idx64) {
    // index values < 2^31: low word suffices for both int32 and int64 layouts
    return idx64 ? ((const int*)p)[2 * i] : ((const int*)p)[i];
}

// ---------------------------------------------------------------------------
// 1) permute: slot edges into per-bucket regions. gridDim.y = relation.
//    relation -> (dst ntype, src table): r0:(B,e0) r1:(A,e1) r2:(A,e2) r3:(B,e3)
//    bucket b = ntype*nN + dst; bit30 of entry selects table (e2/e3 vs e0/e1).
//    Overflow (pos >= KSLOT) goes to the spill list (sized for ALL edges).
// ---------------------------------------------------------------------------
__global__ void __launch_bounds__(256)
permute_kernel(const void* __restrict__ s0, const void* __restrict__ d0,
               const void* __restrict__ s1, const void* __restrict__ d1,
               const void* __restrict__ s2, const void* __restrict__ d2,
               const void* __restrict__ s3, const void* __restrict__ d3,
               int nE, int nN) {
    int e = blockIdx.x * blockDim.x + threadIdx.x;
    if (e >= nE) return;
    int r = blockIdx.y;

    const void* sp; const void* dp; int ntype; int flag;
    switch (r) {
        case 0:  sp = s0; dp = d0; ntype = 1; flag = 0; break;
        case 1:  sp = s1; dp = d1; ntype = 0; flag = 0; break;
        case 2:  sp = s2; dp = d2; ntype = 0; flag = 1; break;
        default: sp = s3; dp = d3; ntype = 1; flag = 1; break;
    }

    const int idx64 = probe_idx64((const unsigned int*)s0);
    int src = load_idx32(sp, e, idx64);
    int dst = load_idx32(dp, e, idx64);
    int b = ntype * nN + dst;
    int ent = src | (flag << 30);

    int pos = atomicAdd(&g_cur[b], 1);
    if (pos < KSLOT) {
        __stcs(&g_entries[b * KSLOT + pos], ent);   // streaming: read-once data
    } else {
        int spos = atomicAdd(&g_nover, 1);
        g_spill[spos] = make_int2(b, ent);
    }
}

// ---------------------------------------------------------------------------
// 2) accumulate: thread = (bucket, float4-chunk). Seed = bias (broadcast),
//    register-accumulate gathered rows, relu, single streaming store.
//    bucket < nN -> h_A (tables e1/e2), else h_B (tables e0/e3).
//    Self-cleaning: restores g_cur / g_nover / g_done to zero for next launch.
// ---------------------------------------------------------------------------
__global__ void __launch_bounds__(256)
accum_kernel(const float* __restrict__ e0, const float* __restrict__ e1,
             const float* __restrict__ e2, const float* __restrict__ e3,
             const float4* __restrict__ bias4, float4* __restrict__ out4,
             int nN) {
    int g = blockIdx.x * blockDim.x + threadIdx.x;
    int b = g >> 4;
    int c = g & 15;
    bool active = (b < 2 * nN);

    int nov = g_nover;   // read BEFORE the end-of-block ticket (see below)

    if (active) {
        const float* t0;
        const float* t1;
        if (b < nN) { t0 = e1; t1 = e2; }      // h_A
        else        { t0 = e0; t1 = e3; }      // h_B

        int n = g_cur[b];                      // whole-warp load ...
        if (c == 0) g_cur[b] = 0;              // ... then predicated reset (safe)
        if (n > KSLOT) n = KSLOT;

        float4 acc = __ldg(&bias4[c]);
        const int* ep = g_entries + b * KSLOT;
        int coff = c * 4;

        #pragma unroll 4
        for (int j = 0; j < n; j++) {
            int ent = __ldcs(&ep[j]);          // streaming: read-once
            const float* tb = (ent & (1 << 30)) ? t1 : t0;
            int src = ent & 0x0FFFFFFF;
            const float4 v =
                *reinterpret_cast<const float4*>(tb + (long long)src * DIM + coff);
            acc.x += v.x; acc.y += v.y; acc.z += v.z; acc.w += v.w;
        }

        // overflow path: never taken in practice
        if (nov > 0) {
            for (int j = 0; j < nov; j++) {
                int2 se = g_spill[j];
                if (se.x == b) {
                    const float* tb = (se.y & (1 << 30)) ? t1 : t0;
                    int src = se.y & 0x0FFFFFFF;
                    const float4 v =
                        *reinterpret_cast<const float4*>(tb + (long long)src * DIM + coff);
                    acc.x += v.x; acc.y += v.y; acc.z += v.z; acc.w += v.w;
                }
            }
        }

        acc.x = fmaxf(acc.x, 0.f);
        acc.y = fmaxf(acc.y, 0.f);
        acc.z = fmaxf(acc.z, 0.f);
        acc.w = fmaxf(acc.w, 0.f);
        __stcs(&out4[(long long)b * CHUNKS + c], acc);   // write-once
    }

    // last-finishing block resets shared counters for the next launch.
    // Every thread consumed its g_nover read before this barrier, so the
    // reset (issued after ALL blocks ticked) cannot precede any read.
    __syncthreads();
    if (threadIdx.x == 0) {
        __threadfence();
        int t = atomicAdd(&g_done, 1);
        if (t == gridDim.x - 1) {
            g_nover = 0;
            g_done  = 0;
        }
    }
}

// ---------------------------------------------------------------------------
// fallback path (atomic scatter, proven) if shapes exceed static scratch
// ---------------------------------------------------------------------------
__global__ void fb_init_kernel(float4* __restrict__ out,
                               const float4* __restrict__ bias4, int n4) {
    int i = blockIdx.x * blockDim.x + threadIdx.x;
    if (i < n4) out[i] = __ldg(&bias4[i & 15]);
}

__global__ void __launch_bounds__(256)
fb_scatter_kernel(const float* __restrict__ e0, const float* __restrict__ e1,
                  const float* __restrict__ e2, const float* __restrict__ e3,
                  const void* __restrict__ s0, const void* __restrict__ d0,
                  const void* __restrict__ s1, const void* __restrict__ d1,
                  const void* __restrict__ s2, const void* __restrict__ d2,
                  const void* __restrict__ s3, const void* __restrict__ d3,
                  float* __restrict__ out, int nE, long long nN) {
    int g = blockIdx.x * blockDim.x + threadIdx.x;
    int edge = g >> 4;
    int c = g & 15;
    if (edge >= nE) return;
    const float* emb; const void* sp; const void* dp; long long off;
    switch (blockIdx.y) {
        case 0:  emb = e0; sp = s0; dp = d0; off = nN * DIM; break;
        case 1:  emb = e1; sp = s1; dp = d1; off = 0;        break;
        case 2:  emb = e2; sp = s2; dp = d2; off = 0;        break;
        default: emb = e3; sp = s3; dp = d3; off = nN * DIM; break;
    }
    const int idx64 = probe_idx64((const unsigned int*)s0);
    long long src = load_idx32(sp, edge, idx64);
    long long dst = load_idx32(dp, edge, idx64);
    const float4 v =
        *reinterpret_cast<const float4*>(emb + src * DIM + (long long)c * 4);
    float* p = out + off + dst * DIM + (long long)c * 4;
    asm volatile("red.global.add.v4.f32 [%0], {%1,%2,%3,%4};"
                 :: "l"(p), "f"(v.x), "f"(v.y), "f"(v.z), "f"(v.w) : "memory");
}

__global__ void fb_relu_kernel(float4* __restrict__ out, int n4) {
    int i = blockIdx.x * blockDim.x + threadIdx.x;
    if (i >= n4) return;
    float4 v = out[i];
    v.x = fmaxf(v.x, 0.f); v.y = fmaxf(v.y, 0.f);
    v.z = fmaxf(v.z, 0.f); v.w = fmaxf(v.w, 0.f);
    out[i] = v;
}

// ---------------------------------------------------------------------------
// kernel_launch — inputs: embed0..3, h_bias, src0,dst0,...,src3,dst3
// ---------------------------------------------------------------------------
extern "C" void kernel_launch(void* const* d_in, const int* in_sizes, int n_in,
                              void* d_out, int out_size) {
    const float* e0 = (const float*)d_in[0];
    const float* e1 = (const float*)d_in[1];
    const float* e2 = (const float*)d_in[2];
    const float* e3 = (const float*)d_in[3];
    const float4* bias4 = (const float4*)d_in[4];

    const int nN = in_sizes[0] / DIM;      // 100000
    const int nE = in_sizes[5];            // 500000
    const int n4 = out_size / 4;           // 2*N*16

    float* out = (float*)d_out;
    const int T = 256;
    const int nb = 2 * nN;

    if (nN <= NMAX && nE <= EMAX) {
        // 1) slot edges into buckets (counters are zero by invariant)
        dim3 gperm((nE + T - 1) / T, 4);
        permute_kernel<<<gperm, T>>>(d_in[5], d_in[6], d_in[7], d_in[8],
                                     d_in[9], d_in[10], d_in[11], d_in[12],
                                     nE, nN);
        // 2) gather-accumulate + bias + relu + store (self-cleans counters)
        int work = nb * CHUNKS;
        accum_kernel<<<(work + T - 1) / T, T>>>(e0, e1, e2, e3, bias4,
                                                (float4*)out, nN);
    } else {
        // fallback: atomic scatter (does not touch the bucket scratch)
        fb_init_kernel<<<(n4 + T - 1) / T, T>>>((float4*)out, bias4, n4);
        int work = nE * CHUNKS;
        dim3 grid((work + T - 1) / T, 4);
        fb_scatter_kernel<<<grid, T>>>(e0, e1, e2, e3,
                                       d_in[5], d_in[6], d_in[7], d_in[8],
                                       d_in[9], d_in[10], d_in[11], d_in[12],
                                       out, nE, nN);
        fb_relu_kernel<<<(n4 + T - 1) / T, T>>>((float4*)out, n4);
    }
}

// round 8
// speedup vs baseline: 1.1472x; 1.1472x over previous
#include <cuda_runtime.h>
#include <cstdint>

#define DIM     64
#define CHUNKS  16            // float4 chunks per row
#define NMAX    100000        // nodes per ntype (static scratch sizing)
#define EMAX    500000        // edges per relation
#define KSLOT   32            // slots per bucket (deg ~Poisson(10)); 128B bucket
#define SPILLC  (4 * EMAX)    // spill capacity = all edges (unconditional)

// ---------------------------------------------------------------------------
// scratch (device globals — zero at module load; kernels restore the all-zero
// invariant before finishing, so every launch/graph replay sees zeros)
// ---------------------------------------------------------------------------
__device__ int  g_nover;                      // overflow edge count
__device__ int  g_done;                       // accum finished-block ticket
__device__ int  g_cur[2 * NMAX];              // per-bucket write cursors
__device__ int  g_entries[2 * NMAX * KSLOT];  // src | (tableFlag<<30)
__device__ int2 g_spill[SPILLC];              // (bucket, src|flag<<30)

// ---------------------------------------------------------------------------
// index helpers. int64 values in [0,1e5): odd 32-bit words are 0.
// int32 random values: P(4 specific words all 0) ~ 1e-20. Broadcast loads.
// ---------------------------------------------------------------------------
__device__ __forceinline__ int probe_idx64(const unsigned int* __restrict__ w) {
    return ((w[1] | w[3] | w[5] | w[7]) == 0u) ? 1 : 0;
}
__device__ __forceinline__ int load_idx32(const void* p, int i, int idx64) {
    // index values < 2^31: low word suffices for both int32 and int64 layouts
    return idx64 ? ((const int*)p)[2 * i] : ((const int*)p)[i];
}

// ---------------------------------------------------------------------------
// 1) permute: slot edges into per-bucket regions. gridDim.y = relation.
//    relation -> (dst ntype, src table): r0:(B,e0) r1:(A,e1) r2:(A,e2) r3:(B,e3)
//    bucket b = ntype*nN + dst; bit30 of entry selects table (e2/e3 vs e0/e1).
//    Overflow (pos >= KSLOT) goes to the spill list (sized for ALL edges).
//    PLAIN stores: entries must stay L2-resident for accum.
// ---------------------------------------------------------------------------
__global__ void __launch_bounds__(256)
permute_kernel(const void* __restrict__ s0, const void* __restrict__ d0,
               const void* __restrict__ s1, const void* __restrict__ d1,
               const void* __restrict__ s2, const void* __restrict__ d2,
               const void* __restrict__ s3, const void* __restrict__ d3,
               int nE, int nN) {
    int e = blockIdx.x * blockDim.x + threadIdx.x;
    if (e >= nE) return;
    int r = blockIdx.y;

    const void* sp; const void* dp; int ntype; int flag;
    switch (r) {
        case 0:  sp = s0; dp = d0; ntype = 1; flag = 0; break;
        case 1:  sp = s1; dp = d1; ntype = 0; flag = 0; break;
        case 2:  sp = s2; dp = d2; ntype = 0; flag = 1; break;
        default: sp = s3; dp = d3; ntype = 1; flag = 1; break;
    }

    const int idx64 = probe_idx64((const unsigned int*)s0);
    int src = load_idx32(sp, e, idx64);
    int dst = load_idx32(dp, e, idx64);
    int b = ntype * nN + dst;
    int ent = src | (flag << 30);

    int pos = atomicAdd(&g_cur[b], 1);
    if (pos < KSLOT) {
        g_entries[b * KSLOT + pos] = ent;
    } else {
        int spos = atomicAdd(&g_nover, 1);
        g_spill[spos] = make_int2(b, ent);
    }
}

// ---------------------------------------------------------------------------
// 2) accumulate: thread = (bucket, float4-chunk). Seed = bias (broadcast),
//    register-accumulate gathered rows, relu, single store.
//    bucket < nN -> h_A (tables e1/e2), else h_B (tables e0/e3).
//    Self-cleaning, FENCE-FREE: g_cur reset after whole-warp read (in-warp
//    program order); g_nover/g_done reset by last-block ticket — all of a
//    block's g_nover reads are ordered before its ticket by __syncthreads(),
//    and cross-launch visibility is given by the kernel boundary.
// ---------------------------------------------------------------------------
__global__ void __launch_bounds__(256)
accum_kernel(const float* __restrict__ e0, const float* __restrict__ e1,
             const float* __restrict__ e2, const float* __restrict__ e3,
             const float4* __restrict__ bias4, float4* __restrict__ out4,
             int nN) {
    int g = blockIdx.x * blockDim.x + threadIdx.x;
    int b = g >> 4;
    int c = g & 15;
    bool active = (b < 2 * nN);

    int nov = g_nover;   // read BEFORE the end-of-block ticket

    if (active) {
        const float* t0;
        const float* t1;
        if (b < nN) { t0 = e1; t1 = e2; }      // h_A
        else        { t0 = e0; t1 = e3; }      // h_B

        int n = g_cur[b];                      // whole-warp load ...
        if (c == 0) g_cur[b] = 0;              // ... then predicated reset
        if (n > KSLOT) n = KSLOT;

        float4 acc = __ldg(&bias4[c]);
        const int* ep = g_entries + b * KSLOT;
        int coff = c * 4;

        #pragma unroll 4
        for (int j = 0; j < n; j++) {
            int ent = ep[j];                   // plain load: L2-resident
            const float* tb = (ent & (1 << 30)) ? t1 : t0;
            int src = ent & 0x0FFFFFFF;
            const float4 v =
                *reinterpret_cast<const float4*>(tb + (long long)src * DIM + coff);
            acc.x += v.x; acc.y += v.y; acc.z += v.z; acc.w += v.w;
        }

        // overflow path: never taken in practice (one broadcast-cached load)
        if (nov > 0) {
            for (int j = 0; j < nov; j++) {
                int2 se = g_spill[j];
                if (se.x == b) {
                    const float* tb = (se.y & (1 << 30)) ? t1 : t0;
                    int src = se.y & 0x0FFFFFFF;
                    const float4 v =
                        *reinterpret_cast<const float4*>(tb + (long long)src * DIM + coff);
                    acc.x += v.x; acc.y += v.y; acc.z += v.z; acc.w += v.w;
                }
            }
        }

        acc.x = fmaxf(acc.x, 0.f);
        acc.y = fmaxf(acc.y, 0.f);
        acc.z = fmaxf(acc.z, 0.f);
        acc.w = fmaxf(acc.w, 0.f);
        out4[(long long)b * CHUNKS + c] = acc;
    }

    // last-finishing block resets the shared counters (no fence: see header)
    __syncthreads();
    if (threadIdx.x == 0) {
        int t = atomicAdd(&g_done, 1);
        if (t == gridDim.x - 1) {
            g_nover = 0;
            g_done  = 0;
        }
    }
}

// ---------------------------------------------------------------------------
// fallback path (atomic scatter, proven) if shapes exceed static scratch
// ---------------------------------------------------------------------------
__global__ void fb_init_kernel(float4* __restrict__ out,
                               const float4* __restrict__ bias4, int n4) {
    int i = blockIdx.x * blockDim.x + threadIdx.x;
    if (i < n4) out[i] = __ldg(&bias4[i & 15]);
}

__global__ void __launch_bounds__(256)
fb_scatter_kernel(const float* __restrict__ e0, const float* __restrict__ e1,
                  const float* __restrict__ e2, const float* __restrict__ e3,
                  const void* __restrict__ s0, const void* __restrict__ d0,
                  const void* __restrict__ s1, const void* __restrict__ d1,
                  const void* __restrict__ s2, const void* __restrict__ d2,
                  const void* __restrict__ s3, const void* __restrict__ d3,
                  float* __restrict__ out, int nE, long long nN) {
    int g = blockIdx.x * blockDim.x + threadIdx.x;
    int edge = g >> 4;
    int c = g & 15;
    if (edge >= nE) return;
    const float* emb; const void* sp; const void* dp; long long off;
    switch (blockIdx.y) {
        case 0:  emb = e0; sp = s0; dp = d0; off = nN * DIM; break;
        case 1:  emb = e1; sp = s1; dp = d1; off = 0;        break;
        case 2:  emb = e2; sp = s2; dp = d2; off = 0;        break;
        default: emb = e3; sp = s3; dp = d3; off = nN * DIM; break;
    }
    const int idx64 = probe_idx64((const unsigned int*)s0);
    long long src = load_idx32(sp, edge, idx64);
    long long dst = load_idx32(dp, edge, idx64);
    const float4 v =
        *reinterpret_cast<const float4*>(emb + src * DIM + (long long)c * 4);
    float* p = out + off + dst * DIM + (long long)c * 4;
    asm volatile("red.global.add.v4.f32 [%0], {%1,%2,%3,%4};"
                 :: "l"(p), "f"(v.x), "f"(v.y), "f"(v.z), "f"(v.w) : "memory");
}

__global__ void fb_relu_kernel(float4* __restrict__ out, int n4) {
    int i = blockIdx.x * blockDim.x + threadIdx.x;
    if (i >= n4) return;
    float4 v = out[i];
    v.x = fmaxf(v.x, 0.f); v.y = fmaxf(v.y, 0.f);
    v.z = fmaxf(v.z, 0.f); v.w = fmaxf(v.w, 0.f);
    out[i] = v;
}

// ---------------------------------------------------------------------------
// kernel_launch — inputs: embed0..3, h_bias, src0,dst0,...,src3,dst3
// ---------------------------------------------------------------------------
extern "C" void kernel_launch(void* const* d_in, const int* in_sizes, int n_in,
                              void* d_out, int out_size) {
    const float* e0 = (const float*)d_in[0];
    const float* e1 = (const float*)d_in[1];
    const float* e2 = (const float*)d_in[2];
    const float* e3 = (const float*)d_in[3];
    const float4* bias4 = (const float4*)d_in[4];

    const int nN = in_sizes[0] / DIM;      // 100000
    const int nE = in_sizes[5];            // 500000
    const int n4 = out_size / 4;           // 2*N*16

    float* out = (float*)d_out;
    const int T = 256;
    const int nb = 2 * nN;

    if (nN <= NMAX && nE <= EMAX) {
        // 1) slot edges into buckets (counters zero by invariant)
        dim3 gperm((nE + T - 1) / T, 4);
        permute_kernel<<<gperm, T>>>(d_in[5], d_in[6], d_in[7], d_in[8],
                                     d_in[9], d_in[10], d_in[11], d_in[12],
                                     nE, nN);
        // 2) gather-accumulate + bias + relu + store (self-cleans counters)
        int work = nb * CHUNKS;
        accum_kernel<<<(work + T - 1) / T, T>>>(e0, e1, e2, e3, bias4,
                                                (float4*)out, nN);
    } else {
        // fallback: atomic scatter (does not touch bucket scratch)
        fb_init_kernel<<<(n4 + T - 1) / T, T>>>((float4*)out, bias4, n4);
        int work = nE * CHUNKS;
        dim3 grid((work + T - 1) / T, 4);
        fb_scatter_kernel<<<grid, T>>>(e0, e1, e2, e3,
                                       d_in[5], d_in[6], d_in[7], d_in[8],
                                       d_in[9], d_in[10], d_in[11], d_in[12],
                                       out, nE, nN);
        fb_relu_kernel<<<(n4 + T - 1) / T, T>>>((float4*)out, n4);
    }
}

// round 9
// speedup vs baseline: 1.1888x; 1.0363x over previous
#include <cuda_runtime.h>
#include <cstdint>

#define DIM     64
#define CHUNKS  16            // float4 chunks per row
#define NMAX    100000        // nodes per ntype (static scratch sizing)
#define EMAX    500000        // edges per relation
#define KSLOT   40            // slots per bucket (deg ~Poisson(10)) — R6 value
#define SPILLC  (4 * EMAX)    // spill capacity = all edges (unconditional)

// ---------------------------------------------------------------------------
// scratch (device globals — zero at module load; kernels restore the all-zero
// invariant before finishing, so every launch/graph replay sees zeros)
// ---------------------------------------------------------------------------
__device__ int  g_nover;                      // overflow edge count
__device__ int  g_done;                       // accum finished-warp ticket
__device__ int  g_cur[2 * NMAX];              // per-bucket write cursors
__device__ int  g_entries[2 * NMAX * KSLOT];  // src | (tableFlag<<30)
__device__ int2 g_spill[SPILLC];              // (bucket, src|flag<<30)

// ---------------------------------------------------------------------------
// index helpers. int64 values in [0,1e5): odd 32-bit words are 0.
// int32 random values: P(4 specific words all 0) ~ 1e-20. Broadcast loads.
// ---------------------------------------------------------------------------
__device__ __forceinline__ int probe_idx64(const unsigned int* __restrict__ w) {
    return ((w[1] | w[3] | w[5] | w[7]) == 0u) ? 1 : 0;
}
__device__ __forceinline__ int load_idx32(const void* p, int i, int idx64) {
    // index values < 2^31: low word suffices for both int32 and int64 layouts
    return idx64 ? ((const int*)p)[2 * i] : ((const int*)p)[i];
}

// ---------------------------------------------------------------------------
// 1) permute: slot edges into per-bucket regions. gridDim.y = relation.
//    relation -> (dst ntype, src table): r0:(B,e0) r1:(A,e1) r2:(A,e2) r3:(B,e3)
//    bucket b = ntype*nN + dst; bit30 of entry selects table (e2/e3 vs e0/e1).
//    Overflow (pos >= KSLOT) goes to the spill list (sized for ALL edges).
// ---------------------------------------------------------------------------
__global__ void __launch_bounds__(256)
permute_kernel(const void* __restrict__ s0, const void* __restrict__ d0,
               const void* __restrict__ s1, const void* __restrict__ d1,
               const void* __restrict__ s2, const void* __restrict__ d2,
               const void* __restrict__ s3, const void* __restrict__ d3,
               int nE, int nN) {
    int e = blockIdx.x * blockDim.x + threadIdx.x;
    if (e >= nE) return;
    int r = blockIdx.y;

    const void* sp; const void* dp; int ntype; int flag;
    switch (r) {
        case 0:  sp = s0; dp = d0; ntype = 1; flag = 0; break;
        case 1:  sp = s1; dp = d1; ntype = 0; flag = 0; break;
        case 2:  sp = s2; dp = d2; ntype = 0; flag = 1; break;
        default: sp = s3; dp = d3; ntype = 1; flag = 1; break;
    }

    const int idx64 = probe_idx64((const unsigned int*)s0);
    int src = load_idx32(sp, e, idx64);
    int dst = load_idx32(dp, e, idx64);
    int b = ntype * nN + dst;
    int ent = src | (flag << 30);

    int pos = atomicAdd(&g_cur[b], 1);
    if (pos < KSLOT) {
        g_entries[b * KSLOT + pos] = ent;
    } else {
        int spos = atomicAdd(&g_nover, 1);
        g_spill[spos] = make_int2(b, ent);
    }
}

// ---------------------------------------------------------------------------
// 2) accumulate: thread = (bucket, float4-chunk). Seed = bias (broadcast),
//    register-accumulate gathered rows, relu, single store. R6 body.
//    Self-cleaning WITHOUT any block barrier (no warp convoy):
//      - g_cur[b]=0 by lane c==0 after the warp's cursor read (same-warp,
//        same-address: LSU processes in issue order; validated in R8).
//      - g_nover/g_done reset by per-warp ticket: each warp ticks only after
//        its nov value is resolved (branch on nov precedes the tick in
//        converged program order), so the final resetter cannot precede any
//        read. Cross-launch visibility via the kernel boundary.
// ---------------------------------------------------------------------------
__global__ void __launch_bounds__(256)
accum_kernel(const float* __restrict__ e0, const float* __restrict__ e1,
             const float* __restrict__ e2, const float* __restrict__ e3,
             const float4* __restrict__ bias4, float4* __restrict__ out4,
             int nN, int nWarps) {
    int g = blockIdx.x * blockDim.x + threadIdx.x;
    int b = g >> 4;
    int c = g & 15;

    int nov = 0;

    if (b < 2 * nN) {
        const float* t0;
        const float* t1;
        if (b < nN) { t0 = e1; t1 = e2; }      // h_A
        else        { t0 = e0; t1 = e3; }      // h_B

        int n = g_cur[b];                      // whole-warp broadcast load ...
        if (c == 0) g_cur[b] = 0;              // ... then predicated reset
        if (n > KSLOT) n = KSLOT;

        float4 acc = __ldg(&bias4[c]);
        const int* ep = g_entries + b * KSLOT;
        int coff = c * 4;

        #pragma unroll 4
        for (int j = 0; j < n; j++) {
            int ent = ep[j];
            const float* tb = (ent & (1 << 30)) ? t1 : t0;
            int src = ent & 0x0FFFFFFF;
            const float4 v =
                *reinterpret_cast<const float4*>(tb + (long long)src * DIM + coff);
            acc.x += v.x; acc.y += v.y; acc.z += v.z; acc.w += v.w;
        }

        // overflow path: never taken in practice (one broadcast-cached load)
        nov = g_nover;
        if (nov > 0) {
            for (int j = 0; j < nov; j++) {
                int2 se = g_spill[j];
                if (se.x == b) {
                    const float* tb = (se.y & (1 << 30)) ? t1 : t0;
                    int src = se.y & 0x0FFFFFFF;
                    const float4 v =
                        *reinterpret_cast<const float4*>(tb + (long long)src * DIM + coff);
                    acc.x += v.x; acc.y += v.y; acc.z += v.z; acc.w += v.w;
                }
            }
        }

        acc.x = fmaxf(acc.x, 0.f);
        acc.y = fmaxf(acc.y, 0.f);
        acc.z = fmaxf(acc.z, 0.f);
        acc.w = fmaxf(acc.w, 0.f);
        out4[(long long)b * CHUNKS + c] = acc;
    } else {
        nov = g_nover;   // keep read-before-tick invariant for edge warps
    }

    // per-warp ticket (no __syncthreads): last warp restores the zero invariant
    if ((threadIdx.x & 31) == 0) {
        int dummy = nov;                 // nov resolved before tick (dep above)
        (void)dummy;
        int t = atomicAdd(&g_done, 1);
        if (t == nWarps - 1) {
            g_nover = 0;
            g_done  = 0;
        }
    }
}

// ---------------------------------------------------------------------------
// fallback path (atomic scatter, proven) if shapes exceed static scratch
// ---------------------------------------------------------------------------
__global__ void fb_init_kernel(float4* __restrict__ out,
                               const float4* __restrict__ bias4, int n4) {
    int i = blockIdx.x * blockDim.x + threadIdx.x;
    if (i < n4) out[i] = __ldg(&bias4[i & 15]);
}

__global__ void __launch_bounds__(256)
fb_scatter_kernel(const float* __restrict__ e0, const float* __restrict__ e1,
                  const float* __restrict__ e2, const float* __restrict__ e3,
                  const void* __restrict__ s0, const void* __restrict__ d0,
                  const void* __restrict__ s1, const void* __restrict__ d1,
                  const void* __restrict__ s2, const void* __restrict__ d2,
                  const void* __restrict__ s3, const void* __restrict__ d3,
                  float* __restrict__ out, int nE, long long nN) {
    int g = blockIdx.x * blockDim.x + threadIdx.x;
    int edge = g >> 4;
    int c = g & 15;
    if (edge >= nE) return;
    const float* emb; const void* sp; const void* dp; long long off;
    switch (blockIdx.y) {
        case 0:  emb = e0; sp = s0; dp = d0; off = nN * DIM; break;
        case 1:  emb = e1; sp = s1; dp = d1; off = 0;        break;
        case 2:  emb = e2; sp = s2; dp = d2; off = 0;        break;
        default: emb = e3; sp = s3; dp = d3; off = nN * DIM; break;
    }
    const int idx64 = probe_idx64((const unsigned int*)s0);
    long long src = load_idx32(sp, edge, idx64);
    long long dst = load_idx32(dp, edge, idx64);
    const float4 v =
        *reinterpret_cast<const float4*>(emb + src * DIM + (long long)c * 4);
    float* p = out + off + dst * DIM + (long long)c * 4;
    asm volatile("red.global.add.v4.f32 [%0], {%1,%2,%3,%4};"
                 :: "l"(p), "f"(v.x), "f"(v.y), "f"(v.z), "f"(v.w) : "memory");
}

__global__ void fb_relu_kernel(float4* __restrict__ out, int n4) {
    int i = blockIdx.x * blockDim.x + threadIdx.x;
    if (i >= n4) return;
    float4 v = out[i];
    v.x = fmaxf(v.x, 0.f); v.y = fmaxf(v.y, 0.f);
    v.z = fmaxf(v.z, 0.f); v.w = fmaxf(v.w, 0.f);
    out[i] = v;
}

// ---------------------------------------------------------------------------
// kernel_launch — inputs: embed0..3, h_bias, src0,dst0,...,src3,dst3
// ---------------------------------------------------------------------------
extern "C" void kernel_launch(void* const* d_in, const int* in_sizes, int n_in,
                              void* d_out, int out_size) {
    const float* e0 = (const float*)d_in[0];
    const float* e1 = (const float*)d_in[1];
    const float* e2 = (const float*)d_in[2];
    const float* e3 = (const float*)d_in[3];
    const float4* bias4 = (const float4*)d_in[4];

    const int nN = in_sizes[0] / DIM;      // 100000
    const int nE = in_sizes[5];            // 500000
    const int n4 = out_size / 4;           // 2*N*16

    float* out = (float*)d_out;
    const int T = 256;
    const int nb = 2 * nN;

    if (nN <= NMAX && nE <= EMAX) {
        // 1) slot edges into buckets (counters zero by invariant)
        dim3 gperm((nE + T - 1) / T, 4);
        permute_kernel<<<gperm, T>>>(d_in[5], d_in[6], d_in[7], d_in[8],
                                     d_in[9], d_in[10], d_in[11], d_in[12],
                                     nE, nN);
        // 2) gather-accumulate + bias + relu + store (warp-level self-clean)
        int work = nb * CHUNKS;
        int blocks = (work + T - 1) / T;
        int nWarps = blocks * (T / 32);
        accum_kernel<<<blocks, T>>>(e0, e1, e2, e3, bias4,
                                    (float4*)out, nN, nWarps);
    } else {
        // fallback: atomic scatter (does not touch bucket scratch)
        fb_init_kernel<<<(n4 + T - 1) / T, T>>>((float4*)out, bias4, n4);
        int work = nE * CHUNKS;
        dim3 grid((work + T - 1) / T, 4);
        fb_scatter_kernel<<<grid, T>>>(e0, e1, e2, e3,
                                       d_in[5], d_in[6], d_in[7], d_in[8],
                                       d_in[9], d_in[10], d_in[11], d_in[12],
                                       out, nE, nN);
        fb_relu_kernel<<<(n4 + T - 1) / T, T>>>((float4*)out, n4);
    }
}

// round 10
// speedup vs baseline: 2.1722x; 1.8271x over previous
#include <cuda_runtime.h>
#include <cstdint>

#define DIM     64
#define CHUNKS  16            // float4 chunks per row
#define NMAX    100000        // nodes per ntype (static scratch sizing)
#define EMAX    500000        // edges per relation
#define KSLOT   40            // slots per bucket (deg ~Poisson(10))
#define SPILLC  (4 * EMAX)    // spill capacity = all edges (unconditional)

// ---------------------------------------------------------------------------
// scratch (device globals — no runtime allocation)
// ---------------------------------------------------------------------------
__device__ int  g_idx64;                      // 0 = int32 indices, 1 = int64
__device__ int  g_nover;                      // overflow edge count
__device__ int  g_cur[2 * NMAX];              // per-bucket write cursors
__device__ int  g_entries[2 * NMAX * KSLOT];  // src | (tableFlag<<30), slotted
__device__ int2 g_spill[SPILLC];              // (bucket, src|flag<<30)

// ---------------------------------------------------------------------------
__device__ __forceinline__ int load_idx32(const void* p, int i, int idx64) {
    // index values < 2^31: low word suffices for both int32 and int64 layouts
    return idx64 ? ((const int*)p)[2 * i] : ((const int*)p)[i];
}

// ---------------------------------------------------------------------------
// 1) init: zero cursors (int4-vectorized) + overflow count, probe idx width.
//    int64 values in [0,1e5): odd 32-bit words are 0; int32 random: ~never.
// ---------------------------------------------------------------------------
__global__ void init_kernel(int nb4, const unsigned int* __restrict__ s0w) {
    int i = blockIdx.x * blockDim.x + threadIdx.x;
    if (i == 0) {
        bool i64 = (s0w[1] == 0u) && (s0w[3] == 0u) &&
                   (s0w[5] == 0u) && (s0w[7] == 0u);
        g_idx64 = i64 ? 1 : 0;
        g_nover = 0;
    }
    if (i < nb4) reinterpret_cast<int4*>(g_cur)[i] = make_int4(0, 0, 0, 0);
}

// ---------------------------------------------------------------------------
// 2) permute: slot edges into per-bucket regions. gridDim.y = relation.
//    relation -> (dst ntype, src table): r0:(B,e0) r1:(A,e1) r2:(A,e2) r3:(B,e3)
//    bucket b = ntype*nN + dst; bit30 of entry selects table (e2/e3 vs e0/e1).
//    Overflow (pos >= KSLOT) goes to the spill list (sized for ALL edges).
// ---------------------------------------------------------------------------
__global__ void __launch_bounds__(256)
permute_kernel(const void* __restrict__ s0, const void* __restrict__ d0,
               const void* __restrict__ s1, const void* __restrict__ d1,
               const void* __restrict__ s2, const void* __restrict__ d2,
               const void* __restrict__ s3, const void* __restrict__ d3,
               int nE, int nN) {
    int e = blockIdx.x * blockDim.x + threadIdx.x;
    if (e >= nE) return;
    int r = blockIdx.y;

    const void* sp; const void* dp; int ntype; int flag;
    switch (r) {
        case 0:  sp = s0; dp = d0; ntype = 1; flag = 0; break;
        case 1:  sp = s1; dp = d1; ntype = 0; flag = 0; break;
        case 2:  sp = s2; dp = d2; ntype = 0; flag = 1; break;
        default: sp = s3; dp = d3; ntype = 1; flag = 1; break;
    }

    const int idx64 = g_idx64;
    int src = load_idx32(sp, e, idx64);
    int dst = load_idx32(dp, e, idx64);
    int b = ntype * nN + dst;
    int ent = src | (flag << 30);

    int pos = atomicAdd(&g_cur[b], 1);
    if (pos < KSLOT) {
        g_entries[b * KSLOT + pos] = ent;
    } else {
        int spos = atomicAdd(&g_nover, 1);   // spill holds ALL edges worst-case
        g_spill[spos] = make_int2(b, ent);
    }
}

// ---------------------------------------------------------------------------
// 3) accumulate: thread = (bucket, float4-chunk). Seed = bias (broadcast),
//    register-accumulate gathered rows, relu, single store.
//    bucket < nN -> h_A (tables e1/e2), else h_B (tables e0/e3).
// ---------------------------------------------------------------------------
__global__ void __launch_bounds__(256)
accum_kernel(const float* __restrict__ e0, const float* __restrict__ e1,
             const float* __restrict__ e2, const float* __restrict__ e3,
             const float4* __restrict__ bias4, float4* __restrict__ out4,
             int nN) {
    int g = blockIdx.x * blockDim.x + threadIdx.x;
    int b = g >> 4;
    int c = g & 15;
    if (b >= 2 * nN) return;

    const float* t0;
    const float* t1;
    if (b < nN) { t0 = e1; t1 = e2; }      // h_A
    else        { t0 = e0; t1 = e3; }      // h_B

    int n = g_cur[b];
    if (n > KSLOT) n = KSLOT;

    float4 acc = __ldg(&bias4[c]);
    const int* ep = g_entries + b * KSLOT;
    int coff = c * 4;

    #pragma unroll 4
    for (int j = 0; j < n; j++) {
        int ent = ep[j];
        const float* tb = (ent & (1 << 30)) ? t1 : t0;
        int src = ent & 0x0FFFFFFF;
        const float4 v =
            *reinterpret_cast<const float4*>(tb + (long long)src * DIM + coff);
        acc.x += v.x; acc.y += v.y; acc.z += v.z; acc.w += v.w;
    }

    // overflow path: never taken in practice (one broadcast-cached load)
    int nov = g_nover;
    if (nov > 0) {
        for (int j = 0; j < nov; j++) {
            int2 se = g_spill[j];
            if (se.x == b) {
                const float* tb = (se.y & (1 << 30)) ? t1 : t0;
                int src = se.y & 0x0FFFFFFF;
                const float4 v =
                    *reinterpret_cast<const float4*>(tb + (long long)src * DIM + coff);
                acc.x += v.x; acc.y += v.y; acc.z += v.z; acc.w += v.w;
            }
        }
    }

    acc.x = fmaxf(acc.x, 0.f);
    acc.y = fmaxf(acc.y, 0.f);
    acc.z = fmaxf(acc.z, 0.f);
    acc.w = fmaxf(acc.w, 0.f);
    out4[(long long)b * CHUNKS + c] = acc;
}

// ---------------------------------------------------------------------------
// fallback path (atomic scatter, proven) if shapes exceed static scratch
// ---------------------------------------------------------------------------
__global__ void fb_init_kernel(float4* __restrict__ out,
                               const float4* __restrict__ bias4, int n4) {
    int i = blockIdx.x * blockDim.x + threadIdx.x;
    if (i < n4) out[i] = __ldg(&bias4[i & 15]);
}

__global__ void __launch_bounds__(256)
fb_scatter_kernel(const float* __restrict__ e0, const float* __restrict__ e1,
                  const float* __restrict__ e2, const float* __restrict__ e3,
                  const void* __restrict__ s0, const void* __restrict__ d0,
                  const void* __restrict__ s1, const void* __restrict__ d1,
                  const void* __restrict__ s2, const void* __restrict__ d2,
                  const void* __restrict__ s3, const void* __restrict__ d3,
                  float* __restrict__ out, int nE, long long nN) {
    int g = blockIdx.x * blockDim.x + threadIdx.x;
    int edge = g >> 4;
    int c = g & 15;
    if (edge >= nE) return;
    const float* emb; const void* sp; const void* dp; long long off;
    switch (blockIdx.y) {
        case 0:  emb = e0; sp = s0; dp = d0; off = nN * DIM; break;
        case 1:  emb = e1; sp = s1; dp = d1; off = 0;        break;
        case 2:  emb = e2; sp = s2; dp = d2; off = 0;        break;
        default: emb = e3; sp = s3; dp = d3; off = nN * DIM; break;
    }
    const int idx64 = g_idx64;
    long long src = load_idx32(sp, edge, idx64);
    long long dst = load_idx32(dp, edge, idx64);
    const float4 v =
        *reinterpret_cast<const float4*>(emb + src * DIM + (long long)c * 4);
    float* p = out + off + dst * DIM + (long long)c * 4;
    asm volatile("red.global.add.v4.f32 [%0], {%1,%2,%3,%4};"
                 :: "l"(p), "f"(v.x), "f"(v.y), "f"(v.z), "f"(v.w) : "memory");
}

__global__ void fb_relu_kernel(float4* __restrict__ out, int n4) {
    int i = blockIdx.x * blockDim.x + threadIdx.x;
    if (i >= n4) return;
    float4 v = out[i];
    v.x = fmaxf(v.x, 0.f); v.y = fmaxf(v.y, 0.f);
    v.z = fmaxf(v.z, 0.f); v.w = fmaxf(v.w, 0.f);
    out[i] = v;
}

// ---------------------------------------------------------------------------
// kernel_launch — inputs: embed0..3, h_bias, src0,dst0,...,src3,dst3
// ---------------------------------------------------------------------------
extern "C" void kernel_launch(void* const* d_in, const int* in_sizes, int n_in,
                              void* d_out, int out_size) {
    const float* e0 = (const float*)d_in[0];
    const float* e1 = (const float*)d_in[1];
    const float* e2 = (const float*)d_in[2];
    const float* e3 = (const float*)d_in[3];
    const float4* bias4 = (const float4*)d_in[4];

    const int nN = in_sizes[0] / DIM;      // 100000
    const int nE = in_sizes[5];            // 500000
    const int n4 = out_size / 4;           // 2*N*16

    float* out = (float*)d_out;
    const int T = 256;
    const int nb = 2 * nN;

    if (nN <= NMAX && nE <= EMAX && (nb % 4) == 0) {
        // 1) zero cursors (vectorized) + probe
        int nb4 = nb / 4;
        init_kernel<<<(nb4 + T - 1) / T, T>>>(nb4, (const unsigned int*)d_in[5]);
        // 2) slot edges into buckets
        dim3 gperm((nE + T - 1) / T, 4);
        permute_kernel<<<gperm, T>>>(d_in[5], d_in[6], d_in[7], d_in[8],
                                     d_in[9], d_in[10], d_in[11], d_in[12],
                                     nE, nN);
        // 3) gather-accumulate + bias + relu + store
        int work = nb * CHUNKS;
        accum_kernel<<<(work + T - 1) / T, T>>>(e0, e1, e2, e3, bias4,
                                                (float4*)out, nN);
    } else {
        // fallback: atomic scatter (init probes idx width only)
        init_kernel<<<1, 32>>>(0, (const unsigned int*)d_in[5]);
        fb_init_kernel<<<(n4 + T - 1) / T, T>>>((float4*)out, bias4, n4);
        int work = nE * CHUNKS;
        dim3 grid((work + T - 1) / T, 4);
        fb_scatter_kernel<<<grid, T>>>(e0, e1, e2, e3,
                                       d_in[5], d_in[6], d_in[7], d_in[8],
                                       d_in[9], d_in[10], d_in[11], d_in[12],
                                       out, nE, nN);
        fb_relu_kernel<<<(n4 + T - 1) / T, T>>>((float4*)out, n4);
    }
}